// round 15
// baseline (speedup 1.0000x reference)
#include <cuda_runtime.h>
#include <cuda_bf16.h>
#include <cstdint>

#define SQ    1024
#define BATCH 2048
#define NB    16          // batch per CTA
#define NCTA  128
#define TPB   256         // 8 warps x 32
#define NSPLIT 15         // 5 matrices x 3 bf16 splits
#define NCACHED 5         // splits resident in SMEM
#define ACACHE_BYTES (NCACHED * 32768)
#define BF_OFF   ACACHE_BYTES            // 10 B-tensor frag arrays, 4KB each
#define SMEM_BYTES (ACACHE_BYTES + 10 * 4096)

// packed A-fragments: [split 15][w 8][c 8][T 32] x 16B
__device__ uint4 g_wpack[NSPLIT * 64 * 32];
__device__ float g_partial[NCTA];

// ---------- helpers ----------
__device__ __forceinline__ float exp_acc(float x) {
    x = fminf(fmaxf(x, -87.0f), 88.0f);
    float n = rintf(x * 1.4426950408889634f);
    float r = fmaf(-n, 0.6931471824645996f, x);
    r = fmaf(-n, -1.9046542743e-09f, r);
    float p = 1.9875691500e-4f;
    p = fmaf(p, r, 1.3981999507e-3f);
    p = fmaf(p, r, 8.3334519073e-3f);
    p = fmaf(p, r, 4.1665795894e-2f);
    p = fmaf(p, r, 1.6666665459e-1f);
    p = fmaf(p, r, 5.0000001201e-1f);
    float e = fmaf(p * r, r, r) + 1.0f;
    return e * __int_as_float(((int)n + 127) << 23);
}
__device__ __forceinline__ float sigmoid_acc(float v) { return 1.0f / (1.0f + exp_acc(-v)); }

// Kahan compensated add: s += v with running compensation c.
__device__ __forceinline__ void kadd(float& s, float& c, float v) {
    float yv = __fadd_rn(v, -c);
    float tt = __fadd_rn(s, yv);
    c = __fadd_rn(__fadd_rn(tt, -s), -yv);
    s = tt;
}

__device__ __forceinline__ void mma16816(float* d, uint4 a, uint32_t b0, uint32_t b1) {
    asm volatile(
        "mma.sync.aligned.m16n8k16.row.col.f32.bf16.bf16.f32 "
        "{%0,%1,%2,%3},{%4,%5,%6,%7},{%8,%9},{%0,%1,%2,%3};"
        : "+f"(d[0]), "+f"(d[1]), "+f"(d[2]), "+f"(d[3])
        : "r"(a.x), "r"(a.y), "r"(a.z), "r"(a.w), "r"(b0), "r"(b1));
}
// both n-tiles (N=16) against one A-frag
__device__ __forceinline__ void mmaP(float* acc, uint4 a, uint4 b) {
    mma16816(acc, a, b.x, b.y);
    mma16816(acc + 4, a, b.z, b.w);
}

// A-frag fetch: cached splits (s<NCACHED) from SMEM, rest from L2
__device__ __forceinline__ uint4 afrag(const char* smemc, int s, int w, int c, int T) {
    size_t off = ((size_t)((s * 64) + (w * 8) + c) * 32 + T) * 16;
    if (s < NCACHED) return *(const uint4*)(smemc + off);
    return __ldg((const uint4*)((const char*)g_wpack + off));
}

// byte offset of element (k,n) of B-tensor t inside the frag region
__device__ __forceinline__ uint32_t bfoff(int t, int k, int n) {
    int c = k >> 4, kk = k & 15;
    int Tp = (n & 7) * 4 + ((kk & 7) >> 1);
    return (uint32_t)(t * 4096 + c * 512 + Tp * 16 + ((n >> 3) << 3) + ((kk >> 3) << 2) + ((kk & 1) << 1));
}
__device__ __forceinline__ uint16_t bfbits(float v) {
    __nv_bfloat16 b = __float2bfloat16_rn(v);
    return *(uint16_t*)&b;
}
__device__ __forceinline__ void split3w(char* bfb, int t0, int k, int n, float v) {
    __nv_bfloat16 h0 = __float2bfloat16_rn(v);
    float f0 = __bfloat162float(h0);
    float r1 = __fadd_rn(v, -f0);
    __nv_bfloat16 h1 = __float2bfloat16_rn(r1);
    float f1 = __bfloat162float(h1);
    __nv_bfloat16 h2 = __float2bfloat16_rn(__fadd_rn(r1, -f1));
    *(uint16_t*)(bfb + bfoff(t0, k, n))     = *(uint16_t*)&h0;
    *(uint16_t*)(bfb + bfoff(t0 + 1, k, n)) = *(uint16_t*)&h1;
    *(uint16_t*)(bfb + bfoff(t0 + 2, k, n)) = *(uint16_t*)&h2;
}

// ---------- pack kernel: weights -> bf16 splits in A-fragment order ----------
__global__ void pack_kernel(const float* __restrict__ W1x,
                            const float* __restrict__ WtauM,
                            const float* __restrict__ WtauAdp) {
    int g = blockIdx.x * blockDim.x + threadIdx.x;
    if (g >= NSPLIT * 64 * 32) return;
    int T = g & 31, c = (g >> 5) & 7, w = (g >> 8) & 7, s = g >> 11;
    int m = s / 3, p = s % 3;
    int r0 = w * 16 + (T >> 2);
    int k0 = c * 16 + (T & 3) * 2;
    uint16_t out[8];
#pragma unroll
    for (int e = 0; e < 8; e++) {
        int r = r0 + ((e >> 1) & 1) * 8;
        int k = k0 + (e & 1) + (e >> 2) * 8;
        float v;
        if (m == 0)      v = W1x[r * 130 + 2 + k];
        else if (m == 1) v = WtauM[r * 256 + k];
        else if (m == 2) v = WtauM[r * 256 + 128 + k];
        else if (m == 3) v = WtauAdp[r * 256 + k];
        else             v = WtauAdp[r * 256 + 128 + k];
        __nv_bfloat16 b0 = __float2bfloat16_rn(v);
        float f0 = __bfloat162float(b0);
        float r1 = __fadd_rn(v, -f0);
        __nv_bfloat16 b1 = __float2bfloat16_rn(r1);
        float f1 = __bfloat162float(b1);
        __nv_bfloat16 b2 = __float2bfloat16_rn(__fadd_rn(r1, -f1));
        __nv_bfloat16 sel = (p == 0) ? b0 : (p == 1) ? b1 : b2;
        out[e] = *(uint16_t*)&sel;
    }
    uint4 pk;
    pk.x = out[0] | ((uint32_t)out[1] << 16);
    pk.y = out[2] | ((uint32_t)out[3] << 16);
    pk.z = out[4] | ((uint32_t)out[5] << 16);
    pk.w = out[6] | ((uint32_t)out[7] << 16);
    g_wpack[g] = pk;
}

// ---------- main persistent RNN kernel ----------
__global__ void __launch_bounds__(TPB, 1)
rnn_kernel(const float* __restrict__ x,   const float* __restrict__ y,
           const float* __restrict__ h0m, const float* __restrict__ h0s,
           const float* __restrict__ h0b,
           const float* __restrict__ W1x, const float* __restrict__ b1x,
           const float* __restrict__ btauM, const float* __restrict__ btauAdp,
           const float* __restrict__ Wlin,  const float* __restrict__ blin) {
    extern __shared__ char smemc[];
    char* bfb = smemc + BF_OFF;
    const int tid = threadIdx.x;
    const int T = tid & 31, w = tid >> 5;
    const int gmb = blockIdx.x * NB;

    // stage cached A splits
    {
        const uint4* src = (const uint4*)g_wpack;
        uint4* dst = (uint4*)smemc;
        for (int i = tid; i < NCACHED * 64 * 32; i += TPB) dst[i] = src[i];
    }

    // cell coordinates: D-frag of warp w covers rows [16w,16w+16), cols 0..15
    const int r0 = w * 16 + (T >> 2);
    const int cb = (T & 3) * 2;
    int rw[8], nn[8];
#pragma unroll
    for (int j = 0; j < 8; j++) {
        int q = j & 3, tile = j >> 2;
        rw[j] = r0 + (q >> 1) * 8;
        nn[j] = cb + (q & 1) + tile * 8;
    }
    // per-row constants (2 rows)
    float b1c[2], bMc[2], bAc[2], wx0[2], wx1[2];
#pragma unroll
    for (int r = 0; r < 2; r++) {
        int h = r0 + r * 8;
        b1c[r] = b1x[h]; bMc[r] = btauM[h]; bAc[r] = btauAdp[h];
        wx0[r] = W1x[h * 130]; wx1[r] = W1x[h * 130 + 1];
    }
    // register state + initial B-tensor image
    float st_m[8], st_b[8], st_s[8];
#pragma unroll
    for (int j = 0; j < 8; j++) {
        size_t o = (size_t)(gmb + nn[j]) * 128 + rw[j];
        st_m[j] = h0m[o]; st_s[j] = h0s[o]; st_b[j] = h0b[o];
        *(uint16_t*)(bfb + bfoff(0, rw[j], nn[j])) = bfbits(st_s[j]);
        split3w(bfb, 4, rw[j], nn[j], st_m[j]);
        split3w(bfb, 7, rw[j], nn[j], st_b[j]);
    }
    __syncthreads();

    float den[8];
    for (int t = 0; t < SQ; t++) {
        // ---- phase 1: dense = W1spk @ spk ----
        // main: fresh per-pair accumulator + Kahan; small: fresh per-pair + plain fold
        float sD[8] = {0,0,0,0,0,0,0,0}, cD[8] = {0,0,0,0,0,0,0,0};
        float aDs[8] = {0,0,0,0,0,0,0,0};
#pragma unroll
        for (int cc = 0; cc < 8; cc += 2) {
            float tD[8] = {0,0,0,0,0,0,0,0};
            float tDs[8] = {0,0,0,0,0,0,0,0};
#pragma unroll
            for (int u = 0; u < 2; u++) {
                int c = cc + u;
                uint4 bs = *(const uint4*)(bfb + c * 512 + T * 16);   // tensor 0 = spk (exact)
                mmaP(tD,  afrag(smemc, 0, w, c, T), bs);
                mmaP(tDs, afrag(smemc, 1, w, c, T), bs);
                mmaP(tDs, afrag(smemc, 2, w, c, T), bs);
            }
#pragma unroll
            for (int j = 0; j < 8; j++) {
                kadd(sD[j], cD[j], tD[j]);
                aDs[j] = __fadd_rn(aDs[j], tDs[j]);
            }
        }
        // epilogue 1: bias + x-part, split den into B-frags
        float2 xv[4];
#pragma unroll
        for (int i = 0; i < 4; i++) {
            int n = cb + (i & 1) + (i >> 1) * 8;
            xv[i] = *(const float2*)&x[((size_t)t * BATCH + gmb + n) * 2];
        }
#pragma unroll
        for (int j = 0; j < 8; j++) {
            int q = j & 3, tile = j >> 2, r = q >> 1;
            float2 xp = xv[tile * 2 + (q & 1)];
            float mainD = __fadd_rn(sD[j], -cD[j]);
            den[j] = (mainD + aDs[j]) + b1c[r] + wx0[r] * xp.x + wx1[r] * xp.y;
            split3w(bfb, 1, rw[j], nn[j], den[j]);
        }
        __syncthreads();   // den frags visible

        // ---- phase 2: tauM / tauA ----
        float sM[8] = {0,0,0,0,0,0,0,0}, cM[8] = {0,0,0,0,0,0,0,0};
        float sA[8] = {0,0,0,0,0,0,0,0}, cA[8] = {0,0,0,0,0,0,0,0};
        float aMs[8] = {0,0,0,0,0,0,0,0}, aAs[8] = {0,0,0,0,0,0,0,0};
#pragma unroll
        for (int cc = 0; cc < 8; cc += 2) {
            float tM[8] = {0,0,0,0,0,0,0,0}, tA[8] = {0,0,0,0,0,0,0,0};
            float tMs[8] = {0,0,0,0,0,0,0,0}, tAs[8] = {0,0,0,0,0,0,0,0};
#pragma unroll
            for (int u = 0; u < 2; u++) {
                int c = cc + u;
                const char* bc = bfb + c * 512 + T * 16;
                uint4 d0 = *(const uint4*)(bc + 1 * 4096);
                uint4 d1 = *(const uint4*)(bc + 2 * 4096);
                uint4 d2 = *(const uint4*)(bc + 3 * 4096);
                uint4 m0 = *(const uint4*)(bc + 4 * 4096);
                uint4 m1 = *(const uint4*)(bc + 5 * 4096);
                uint4 m2 = *(const uint4*)(bc + 6 * 4096);
                uint4 e0 = *(const uint4*)(bc + 7 * 4096);
                uint4 e1 = *(const uint4*)(bc + 8 * 4096);
                uint4 e2 = *(const uint4*)(bc + 9 * 4096);
                uint4 md0 = afrag(smemc, 3, w, c, T),  md1 = afrag(smemc, 4, w, c, T),  md2 = afrag(smemc, 5, w, c, T);
                uint4 mm0 = afrag(smemc, 6, w, c, T),  mm1 = afrag(smemc, 7, w, c, T),  mm2 = afrag(smemc, 8, w, c, T);
                uint4 ad0 = afrag(smemc, 9, w, c, T),  ad1 = afrag(smemc, 10, w, c, T), ad2 = afrag(smemc, 11, w, c, T);
                uint4 ab0 = afrag(smemc, 12, w, c, T), ab1 = afrag(smemc, 13, w, c, T), ab2 = afrag(smemc, 14, w, c, T);
                // main terms into pair accumulators
                mmaP(tM, md0, d0);
                mmaP(tM, mm0, m0);
                mmaP(tA, ad0, d0);
                mmaP(tA, ab0, e0);
                // small cross terms into pair accumulators (chain depth 20, not 160)
                mmaP(tMs, md0, d1); mmaP(tMs, md1, d0);
                mmaP(tMs, md0, d2); mmaP(tMs, md1, d1); mmaP(tMs, md2, d0);
                mmaP(tMs, mm0, m1); mmaP(tMs, mm1, m0);
                mmaP(tMs, mm0, m2); mmaP(tMs, mm1, m1); mmaP(tMs, mm2, m0);
                mmaP(tAs, ad0, d1); mmaP(tAs, ad1, d0);
                mmaP(tAs, ad0, d2); mmaP(tAs, ad1, d1); mmaP(tAs, ad2, d0);
                mmaP(tAs, ab0, e1); mmaP(tAs, ab1, e0);
                mmaP(tAs, ab0, e2); mmaP(tAs, ab1, e1); mmaP(tAs, ab2, e0);
            }
#pragma unroll
            for (int j = 0; j < 8; j++) {
                kadd(sM[j], cM[j], tM[j]);
                kadd(sA[j], cA[j], tA[j]);
                aMs[j] = __fadd_rn(aMs[j], tMs[j]);
                aAs[j] = __fadd_rn(aAs[j], tAs[j]);
            }
        }
        __syncthreads();   // all B reads done before state rewrites

        // ---- epilogue 2: sigmoids + state update + B rewrite ----
#pragma unroll
        for (int j = 0; j < 8; j++) {
            int r = (j & 3) >> 1;
            float mM = __fadd_rn(sM[j], -cM[j]);
            float mA = __fadd_rn(sA[j], -cA[j]);
            float tm = sigmoid_acc((mM + aMs[j]) + bMc[r]);
            float ta = sigmoid_acc((mA + aAs[j]) + bAc[r]);
            float bbn = ta * st_b[j] + (1.0f - ta) * st_s[j];
            float Bth = 0.01f + 1.8f * bbn;
            float mn = st_m[j] * tm + (1.0f - tm) * den[j] - Bth * st_s[j];
            float sn = (mn - Bth) > 0.0f ? 1.0f : 0.0f;
            st_m[j] = mn; st_b[j] = bbn; st_s[j] = sn;
            *(uint16_t*)(bfb + bfoff(0, rw[j], nn[j])) = bfbits(sn);
            split3w(bfb, 4, rw[j], nn[j], mn);
            split3w(bfb, 7, rw[j], nn[j], bbn);
        }
        __syncthreads();
    }

    // ---- readout ----
    float* Sm = (float*)smemc;   // reuse (A cache dead now)
#pragma unroll
    for (int j = 0; j < 8; j++) Sm[rw[j] * 16 + nn[j]] = st_m[j];
    __syncthreads();
    if (tid < NB) {
        float o = blin[0];
        for (int h = 0; h < 128; h++) o += Sm[h * 16 + tid] * Wlin[h];
        float d = o - y[gmb + tid];
        Sm[2048 + tid] = d * d;
    }
    __syncthreads();
    if (tid == 0) {
        float s = 0.0f;
        for (int i = 0; i < NB; i++) s += Sm[2048 + i];
        g_partial[blockIdx.x] = s;
    }
}

__global__ void reduce_kernel(float* out) {
    __shared__ float sb[NCTA];
    sb[threadIdx.x] = g_partial[threadIdx.x];
    __syncthreads();
    if (threadIdx.x == 0) {
        float s = 0.0f;
        for (int i = 0; i < NCTA; i++) s += sb[i];
        out[0] = s / (float)BATCH;
    }
}

extern "C" void kernel_launch(void* const* d_in, const int* in_sizes, int n_in,
                              void* d_out, int out_size) {
    const float* x       = (const float*)d_in[0];
    const float* y       = (const float*)d_in[1];
    const float* h0_mem  = (const float*)d_in[2];
    const float* h0_spk  = (const float*)d_in[3];
    const float* h0_b    = (const float*)d_in[4];
    const float* W1x     = (const float*)d_in[5];
    const float* b1x     = (const float*)d_in[6];
    const float* WtauM   = (const float*)d_in[7];
    const float* btauM   = (const float*)d_in[8];
    const float* WtauAdp = (const float*)d_in[9];
    const float* btauAdp = (const float*)d_in[10];
    const float* Wlin    = (const float*)d_in[11];
    const float* blin    = (const float*)d_in[12];

    static int attr_set = 0;
    if (!attr_set) {
        cudaFuncSetAttribute(rnn_kernel, cudaFuncAttributeMaxDynamicSharedMemorySize, SMEM_BYTES);
        attr_set = 1;
    }
    pack_kernel<<<(NSPLIT * 64 * 32 + 255) / 256, 256>>>(W1x, WtauM, WtauAdp);
    rnn_kernel<<<NCTA, TPB, SMEM_BYTES>>>(x, y, h0_mem, h0_spk, h0_b,
                                          W1x, b1x, btauM, btauAdp, Wlin, blin);
    reduce_kernel<<<1, NCTA>>>((float*)d_out);
}

// round 16
// speedup vs baseline: 1.2596x; 1.2596x over previous
#include <cuda_runtime.h>
#include <cuda_bf16.h>
#include <cstdint>

#define SQ    1024
#define BATCH 2048
#define NB    16          // batch per CTA
#define NCTA  128
#define TPB   256         // 8 warps x 32
#define NSPLIT 15         // 5 matrices x 3 bf16 splits: W1(0-2) C1(3-5) MM(6-8) C2(9-11) AB(12-14)
#define NCACHED 6         // splits resident in SMEM (W1 x3 + C1 x3)
#define ACACHE_BYTES (NCACHED * 32768)
#define BF_OFF   ACACHE_BYTES            // 7 B-tensor frag arrays, 4KB each
#define SMEM_BYTES (ACACHE_BYTES + 7 * 4096)

// packed A-fragments: [split 15][w 8][c 8][T 32] x 16B
__device__ uint4 g_wpack[NSPLIT * 64 * 32];
__device__ double g_C1[128 * 128];   // WtauM[:, :128] @ W1x[:, 2:130]
__device__ double g_C2[128 * 128];   // WtauAdp[:, :128] @ W1x[:, 2:130]
__device__ float g_vec[6 * 128];     // vM,uM0,uM1,vA,uA0,uA1
__device__ float g_partial[NCTA];

// ---------- helpers ----------
__device__ __forceinline__ float exp_acc(float x) {
    x = fminf(fmaxf(x, -87.0f), 88.0f);
    float n = rintf(x * 1.4426950408889634f);
    float r = fmaf(-n, 0.6931471824645996f, x);
    r = fmaf(-n, -1.9046542743e-09f, r);
    float p = 1.9875691500e-4f;
    p = fmaf(p, r, 1.3981999507e-3f);
    p = fmaf(p, r, 8.3334519073e-3f);
    p = fmaf(p, r, 4.1665795894e-2f);
    p = fmaf(p, r, 1.6666665459e-1f);
    p = fmaf(p, r, 5.0000001201e-1f);
    float e = fmaf(p * r, r, r) + 1.0f;
    return e * __int_as_float(((int)n + 127) << 23);
}
__device__ __forceinline__ float sigmoid_acc(float v) { return 1.0f / (1.0f + exp_acc(-v)); }

// Kahan compensated add: s += v with running compensation c.
__device__ __forceinline__ void kadd(float& s, float& c, float v) {
    float yv = __fadd_rn(v, -c);
    float tt = __fadd_rn(s, yv);
    c = __fadd_rn(__fadd_rn(tt, -s), -yv);
    s = tt;
}

__device__ __forceinline__ void mma16816(float* d, uint4 a, uint32_t b0, uint32_t b1) {
    asm volatile(
        "mma.sync.aligned.m16n8k16.row.col.f32.bf16.bf16.f32 "
        "{%0,%1,%2,%3},{%4,%5,%6,%7},{%8,%9},{%0,%1,%2,%3};"
        : "+f"(d[0]), "+f"(d[1]), "+f"(d[2]), "+f"(d[3])
        : "r"(a.x), "r"(a.y), "r"(a.z), "r"(a.w), "r"(b0), "r"(b1));
}
__device__ __forceinline__ void mmaP(float* acc, uint4 a, uint4 b) {
    mma16816(acc, a, b.x, b.y);
    mma16816(acc + 4, a, b.z, b.w);
}

// A-frag fetch: cached splits (s<NCACHED) from SMEM, rest from L2
__device__ __forceinline__ uint4 afrag(const char* smemc, int s, int w, int c, int T) {
    size_t off = ((size_t)((s * 64) + (w * 8) + c) * 32 + T) * 16;
    if (s < NCACHED) return *(const uint4*)(smemc + off);
    return __ldg((const uint4*)((const char*)g_wpack + off));
}

// byte offset of element (k,n) of B-tensor t inside the frag region
__device__ __forceinline__ uint32_t bfoff(int t, int k, int n) {
    int c = k >> 4, kk = k & 15;
    int Tp = (n & 7) * 4 + ((kk & 7) >> 1);
    return (uint32_t)(t * 4096 + c * 512 + Tp * 16 + ((n >> 3) << 3) + ((kk >> 3) << 2) + ((kk & 1) << 1));
}
__device__ __forceinline__ uint16_t bfbits(float v) {
    __nv_bfloat16 b = __float2bfloat16_rn(v);
    return *(uint16_t*)&b;
}
__device__ __forceinline__ void split3w(char* bfb, int t0, int k, int n, float v) {
    __nv_bfloat16 h0 = __float2bfloat16_rn(v);
    float f0 = __bfloat162float(h0);
    float r1 = __fadd_rn(v, -f0);
    __nv_bfloat16 h1 = __float2bfloat16_rn(r1);
    float f1 = __bfloat162float(h1);
    __nv_bfloat16 h2 = __float2bfloat16_rn(__fadd_rn(r1, -f1));
    *(uint16_t*)(bfb + bfoff(t0, k, n))     = *(uint16_t*)&h0;
    *(uint16_t*)(bfb + bfoff(t0 + 1, k, n)) = *(uint16_t*)&h1;
    *(uint16_t*)(bfb + bfoff(t0 + 2, k, n)) = *(uint16_t*)&h2;
}

// ---------- precompute: C1 = MD@W1spk, C2 = AD@W1spk (fp64), plus affine vectors ----------
__global__ void precompute_kernel(const float* __restrict__ W1x, const float* __restrict__ b1x,
                                  const float* __restrict__ WtauM, const float* __restrict__ btauM,
                                  const float* __restrict__ WtauAdp, const float* __restrict__ btauAdp) {
    int r = blockIdx.x;      // output row h
    int k = threadIdx.x;     // column
    double s1 = 0.0, s2 = 0.0;
    for (int j = 0; j < 128; j++) {
        double wv = (double)W1x[j * 130 + 2 + k];
        s1 += (double)WtauM[r * 256 + j]   * wv;
        s2 += (double)WtauAdp[r * 256 + j] * wv;
    }
    g_C1[r * 128 + k] = s1;
    g_C2[r * 128 + k] = s2;
    if (k < 6) {
        int col = (k < 3) ? k : k - 3;   // 0: b1x, 1: wx0, 2: wx1
        double s = 0.0;
        for (int j = 0; j < 128; j++) {
            double md = (k < 3) ? (double)WtauM[r * 256 + j] : (double)WtauAdp[r * 256 + j];
            double src = (col == 0) ? (double)b1x[j] : (double)W1x[j * 130 + (col - 1)];
            s += md * src;
        }
        if (k == 0)      g_vec[0 * 128 + r] = (float)(s + (double)btauM[r]);
        else if (k == 1) g_vec[1 * 128 + r] = (float)s;
        else if (k == 2) g_vec[2 * 128 + r] = (float)s;
        else if (k == 3) g_vec[3 * 128 + r] = (float)(s + (double)btauAdp[r]);
        else if (k == 4) g_vec[4 * 128 + r] = (float)s;
        else             g_vec[5 * 128 + r] = (float)s;
    }
}

// ---------- pack kernel: weights (incl fp64 C1/C2) -> bf16 splits in A-fragment order ----------
__global__ void pack_kernel(const float* __restrict__ W1x,
                            const float* __restrict__ WtauM,
                            const float* __restrict__ WtauAdp) {
    int g = blockIdx.x * blockDim.x + threadIdx.x;
    if (g >= NSPLIT * 64 * 32) return;
    int T = g & 31, c = (g >> 5) & 7, w = (g >> 8) & 7, s = g >> 11;
    int m = s / 3, p = s % 3;
    int r0 = w * 16 + (T >> 2);
    int k0 = c * 16 + (T & 3) * 2;
    uint16_t out[8];
#pragma unroll
    for (int e = 0; e < 8; e++) {
        int r = r0 + ((e >> 1) & 1) * 8;
        int k = k0 + (e & 1) + (e >> 2) * 8;
        double dv;
        if (m == 0)      dv = (double)W1x[r * 130 + 2 + k];
        else if (m == 1) dv = g_C1[r * 128 + k];
        else if (m == 2) dv = (double)WtauM[r * 256 + 128 + k];
        else if (m == 3) dv = g_C2[r * 128 + k];
        else             dv = (double)WtauAdp[r * 256 + 128 + k];
        __nv_bfloat16 b0 = __float2bfloat16_rn((float)dv);
        double r1 = dv - (double)__bfloat162float(b0);
        __nv_bfloat16 b1 = __float2bfloat16_rn((float)r1);
        double r2 = r1 - (double)__bfloat162float(b1);
        __nv_bfloat16 b2 = __float2bfloat16_rn((float)r2);
        __nv_bfloat16 sel = (p == 0) ? b0 : (p == 1) ? b1 : b2;
        out[e] = *(uint16_t*)&sel;
    }
    uint4 pk;
    pk.x = out[0] | ((uint32_t)out[1] << 16);
    pk.y = out[2] | ((uint32_t)out[3] << 16);
    pk.z = out[4] | ((uint32_t)out[5] << 16);
    pk.w = out[6] | ((uint32_t)out[7] << 16);
    g_wpack[g] = pk;
}

// ---------- main persistent RNN kernel ----------
// B tensors: 0=spk (exact), 1-3=mem splits, 4-6=bb splits  (den never shared!)
__global__ void __launch_bounds__(TPB, 1)
rnn_kernel(const float* __restrict__ x,   const float* __restrict__ y,
           const float* __restrict__ h0m, const float* __restrict__ h0s,
           const float* __restrict__ h0b,
           const float* __restrict__ W1x, const float* __restrict__ b1x,
           const float* __restrict__ Wlin,  const float* __restrict__ blin) {
    extern __shared__ char smemc[];
    char* bfb = smemc + BF_OFF;
    const int tid = threadIdx.x;
    const int T = tid & 31, w = tid >> 5;
    const int gmb = blockIdx.x * NB;

    // stage cached A splits (s0-5: W1 x3, C1 x3)
    {
        const uint4* src = (const uint4*)g_wpack;
        uint4* dst = (uint4*)smemc;
        for (int i = tid; i < NCACHED * 64 * 32; i += TPB) dst[i] = src[i];
    }

    const int r0 = w * 16 + (T >> 2);
    const int cb = (T & 3) * 2;
    int rw[8], nn[8];
#pragma unroll
    for (int j = 0; j < 8; j++) {
        int q = j & 3, tile = j >> 2;
        rw[j] = r0 + (q >> 1) * 8;
        nn[j] = cb + (q & 1) + tile * 8;
    }
    // per-row constants (2 rows each)
    float b1c[2], wx0[2], wx1[2];
    float vM[2], uM0[2], uM1[2], vA[2], uA0[2], uA1[2];
#pragma unroll
    for (int r = 0; r < 2; r++) {
        int h = r0 + r * 8;
        b1c[r] = b1x[h];
        wx0[r] = W1x[h * 130]; wx1[r] = W1x[h * 130 + 1];
        vM[r]  = g_vec[0 * 128 + h]; uM0[r] = g_vec[1 * 128 + h]; uM1[r] = g_vec[2 * 128 + h];
        vA[r]  = g_vec[3 * 128 + h]; uA0[r] = g_vec[4 * 128 + h]; uA1[r] = g_vec[5 * 128 + h];
    }
    // register state + initial B-tensor image
    float st_m[8], st_b[8], st_s[8];
#pragma unroll
    for (int j = 0; j < 8; j++) {
        size_t o = (size_t)(gmb + nn[j]) * 128 + rw[j];
        st_m[j] = h0m[o]; st_s[j] = h0s[o]; st_b[j] = h0b[o];
        *(uint16_t*)(bfb + bfoff(0, rw[j], nn[j])) = bfbits(st_s[j]);
        split3w(bfb, 1, rw[j], nn[j], st_m[j]);
        split3w(bfb, 4, rw[j], nn[j], st_b[j]);
    }
    __syncthreads();

    for (int t = 0; t < SQ; t++) {
        // x_t for my batch columns
        float2 xv[4];
#pragma unroll
        for (int i = 0; i < 4; i++) {
            int n = cb + (i & 1) + (i >> 1) * 8;
            xv[i] = *(const float2*)&x[((size_t)t * BATCH + gmb + n) * 2];
        }

        // ---- phase 1: den = W1spk @ spk (bit-identical structure to R13) ----
        float den[8];
        {
            float sD[8] = {0,0,0,0,0,0,0,0}, cD[8] = {0,0,0,0,0,0,0,0};
            float aDs[8] = {0,0,0,0,0,0,0,0};
#pragma unroll
            for (int cc = 0; cc < 8; cc += 2) {
                float tD[8] = {0,0,0,0,0,0,0,0};
#pragma unroll
                for (int u = 0; u < 2; u++) {
                    int c = cc + u;
                    uint4 bs = *(const uint4*)(bfb + c * 512 + T * 16);   // spk (exact)
                    mmaP(tD,  afrag(smemc, 0, w, c, T), bs);
                    mmaP(aDs, afrag(smemc, 1, w, c, T), bs);
                    mmaP(aDs, afrag(smemc, 2, w, c, T), bs);
                }
#pragma unroll
                for (int j = 0; j < 8; j++) kadd(sD[j], cD[j], tD[j]);
            }
#pragma unroll
            for (int j = 0; j < 8; j++) {
                int q = j & 3, tile = j >> 2, r = q >> 1;
                float2 xp = xv[tile * 2 + (q & 1)];
                float mainD = __fadd_rn(sD[j], -cD[j]);
                den[j] = (mainD + aDs[j]) + b1c[r] + wx0[r] * xp.x + wx1[r] * xp.y;
            }
        }

        // ---- phase 2: tauM/tauA pre-acts = C@spk + W@state ----
        float sM[8] = {0,0,0,0,0,0,0,0}, cM[8] = {0,0,0,0,0,0,0,0};
        float sA[8] = {0,0,0,0,0,0,0,0}, cA[8] = {0,0,0,0,0,0,0,0};
        float aMs[8] = {0,0,0,0,0,0,0,0}, aAs[8] = {0,0,0,0,0,0,0,0};
#pragma unroll
        for (int cc = 0; cc < 8; cc += 2) {
            float tM[8] = {0,0,0,0,0,0,0,0}, tA[8] = {0,0,0,0,0,0,0,0};
#pragma unroll
            for (int u = 0; u < 2; u++) {
                int c = cc + u;
                const char* bc = bfb + c * 512 + T * 16;
                uint4 bs = *(const uint4*)(bc + 0 * 4096);
                uint4 m0 = *(const uint4*)(bc + 1 * 4096);
                uint4 m1 = *(const uint4*)(bc + 2 * 4096);
                uint4 m2 = *(const uint4*)(bc + 3 * 4096);
                uint4 e0 = *(const uint4*)(bc + 4 * 4096);
                uint4 e1 = *(const uint4*)(bc + 5 * 4096);
                uint4 e2 = *(const uint4*)(bc + 6 * 4096);
                uint4 c10 = afrag(smemc, 3, w, c, T),  c11 = afrag(smemc, 4, w, c, T),  c12 = afrag(smemc, 5, w, c, T);
                uint4 mm0 = afrag(smemc, 6, w, c, T),  mm1 = afrag(smemc, 7, w, c, T),  mm2 = afrag(smemc, 8, w, c, T);
                uint4 c20 = afrag(smemc, 9, w, c, T),  c21 = afrag(smemc, 10, w, c, T), c22 = afrag(smemc, 11, w, c, T);
                uint4 ab0 = afrag(smemc, 12, w, c, T), ab1 = afrag(smemc, 13, w, c, T), ab2 = afrag(smemc, 14, w, c, T);
                // main terms into pair accumulators
                mmaP(tM, c10, bs);
                mmaP(tM, mm0, m0);
                mmaP(tA, c20, bs);
                mmaP(tA, ab0, e0);
                // small terms: C splits vs exact spk (2 each); state 5-term cross set
                mmaP(aMs, c11, bs); mmaP(aMs, c12, bs);
                mmaP(aMs, mm0, m1); mmaP(aMs, mm1, m0);
                mmaP(aMs, mm0, m2); mmaP(aMs, mm1, m1); mmaP(aMs, mm2, m0);
                mmaP(aAs, c21, bs); mmaP(aAs, c22, bs);
                mmaP(aAs, ab0, e1); mmaP(aAs, ab1, e0);
                mmaP(aAs, ab0, e2); mmaP(aAs, ab1, e1); mmaP(aAs, ab2, e0);
            }
#pragma unroll
            for (int j = 0; j < 8; j++) {
                kadd(sM[j], cM[j], tM[j]);
                kadd(sA[j], cA[j], tA[j]);
            }
        }
        __syncthreads();   // all B reads done before state rewrites

        // ---- epilogue: sigmoids (with affine x/bias correction) + state update + B rewrite ----
#pragma unroll
        for (int j = 0; j < 8; j++) {
            int q = j & 3, tile = j >> 2, r = q >> 1;
            float2 xp = xv[tile * 2 + (q & 1)];
            float mM = __fadd_rn(sM[j], -cM[j]);
            float mA = __fadd_rn(sA[j], -cA[j]);
            float tm = sigmoid_acc((mM + aMs[j]) + (vM[r] + uM0[r] * xp.x + uM1[r] * xp.y));
            float ta = sigmoid_acc((mA + aAs[j]) + (vA[r] + uA0[r] * xp.x + uA1[r] * xp.y));
            float bbn = ta * st_b[j] + (1.0f - ta) * st_s[j];
            float Bth = 0.01f + 1.8f * bbn;
            float mn = st_m[j] * tm + (1.0f - tm) * den[j] - Bth * st_s[j];
            float sn = (mn - Bth) > 0.0f ? 1.0f : 0.0f;
            st_m[j] = mn; st_b[j] = bbn; st_s[j] = sn;
            *(uint16_t*)(bfb + bfoff(0, rw[j], nn[j])) = bfbits(sn);
            split3w(bfb, 1, rw[j], nn[j], mn);
            split3w(bfb, 4, rw[j], nn[j], bbn);
        }
        __syncthreads();
    }

    // ---- readout ----
    float* Sm = (float*)smemc;   // reuse (A cache dead now)
#pragma unroll
    for (int j = 0; j < 8; j++) Sm[rw[j] * 16 + nn[j]] = st_m[j];
    __syncthreads();
    if (tid < NB) {
        float o = blin[0];
        for (int h = 0; h < 128; h++) o += Sm[h * 16 + tid] * Wlin[h];
        float d = o - y[gmb + tid];
        Sm[2048 + tid] = d * d;
    }
    __syncthreads();
    if (tid == 0) {
        float s = 0.0f;
        for (int i = 0; i < NB; i++) s += Sm[2048 + i];
        g_partial[blockIdx.x] = s;
    }
}

__global__ void reduce_kernel(float* out) {
    __shared__ float sb[NCTA];
    sb[threadIdx.x] = g_partial[threadIdx.x];
    __syncthreads();
    if (threadIdx.x == 0) {
        float s = 0.0f;
        for (int i = 0; i < NCTA; i++) s += sb[i];
        out[0] = s / (float)BATCH;
    }
}

extern "C" void kernel_launch(void* const* d_in, const int* in_sizes, int n_in,
                              void* d_out, int out_size) {
    const float* x       = (const float*)d_in[0];
    const float* y       = (const float*)d_in[1];
    const float* h0_mem  = (const float*)d_in[2];
    const float* h0_spk  = (const float*)d_in[3];
    const float* h0_b    = (const float*)d_in[4];
    const float* W1x     = (const float*)d_in[5];
    const float* b1x     = (const float*)d_in[6];
    const float* WtauM   = (const float*)d_in[7];
    const float* btauM   = (const float*)d_in[8];
    const float* WtauAdp = (const float*)d_in[9];
    const float* btauAdp = (const float*)d_in[10];
    const float* Wlin    = (const float*)d_in[11];
    const float* blin    = (const float*)d_in[12];

    static int attr_set = 0;
    if (!attr_set) {
        cudaFuncSetAttribute(rnn_kernel, cudaFuncAttributeMaxDynamicSharedMemorySize, SMEM_BYTES);
        attr_set = 1;
    }
    precompute_kernel<<<128, 128>>>(W1x, b1x, WtauM, btauM, WtauAdp, btauAdp);
    pack_kernel<<<(NSPLIT * 64 * 32 + 255) / 256, 256>>>(W1x, WtauM, WtauAdp);
    rnn_kernel<<<NCTA, TPB, SMEM_BYTES>>>(x, y, h0_mem, h0_spk, h0_b,
                                          W1x, b1x, Wlin, blin);
    reduce_kernel<<<1, NCTA>>>((float*)d_out);
}